// round 6
// baseline (speedup 1.0000x reference)
#include <cuda_runtime.h>
#include <cuda_bf16.h>

// out[n, j] = x[n, j] + (1/512) * sum_{k=512..1023} x[n, k]
// x: [131072, 1024] f32, out: [131072, 512] f32
//
// 256-thread block = 2 INDEPENDENT 128-thread row groups.
// Each group syncs with its own named barrier (bar.sync id, 128), so the two
// rows never wait on each other (R1's decoupling + R3's larger-block shape).
// Plain cache policy everywhere (measured best across R1/R3/R4/R5).

static constexpr int ROW_IN  = 1024;
static constexpr int ROW_OUT = 512;
static constexpr int THREADS = 256;

__global__ __launch_bounds__(THREADS)
void projection_kernel(const float* __restrict__ x,
                       float* __restrict__ out)
{
    int sub  = threadIdx.x >> 7;           // row group 0/1
    int tid  = threadIdx.x & 127;          // 0..127 within group
    int lane = threadIdx.x & 31;
    int warp = (threadIdx.x >> 5) & 3;     // warp within group

    size_t row = (size_t)blockIdx.x * 2 + sub;

    const float4* xrow = reinterpret_cast<const float4*>(x + row * ROW_IN);
    float4*       orow = reinterpret_cast<float4*>(out + row * ROW_OUT);

    // front-batch both loads (MLP_p1 = 2)
    float4 t = xrow[128 + tid];   // tail, feeds reduction
    float4 h = xrow[tid];         // head, held for the add

    float s = (t.x + t.y) + (t.z + t.w);

    #pragma unroll
    for (int off = 16; off > 0; off >>= 1)
        s += __shfl_xor_sync(0xFFFFFFFFu, s, off);

    __shared__ float partial[2][4];
    if (lane == 0) partial[sub][warp] = s;

    // per-row-group named barrier: group 0 -> id 1, group 1 -> id 2
    asm volatile("bar.sync %0, 128;" :: "r"(sub + 1) : "memory");

    float total = (partial[sub][0] + partial[sub][1])
                + (partial[sub][2] + partial[sub][3]);
    float mean = total * (1.0f / 512.0f);

    h.x += mean; h.y += mean; h.z += mean; h.w += mean;

    orow[tid] = h;
}

extern "C" void kernel_launch(void* const* d_in, const int* in_sizes, int n_in,
                              void* d_out, int out_size)
{
    const float* x = (const float*)d_in[0];
    float* out = (float*)d_out;

    int n_rows = in_sizes[0] / ROW_IN;   // 131072, even
    int blocks = n_rows / 2;             // 65536

    projection_kernel<<<blocks, THREADS>>>(x, out);
}

// round 7
// speedup vs baseline: 1.2147x; 1.2147x over previous
#include <cuda_runtime.h>
#include <cuda_bf16.h>

// out[n, j] = x[n, j] + (1/512) * sum_{k=512..1023} x[n, k]
// x: [131072, 1024] f32, out: [131072, 512] f32
//
// Best-measured combination:
//   - R3's shape: 256-thread block = 2 rows x 128 threads, ONE __syncthreads
//     (best wall time measured: 114.8us)
//   - R1/R5's cache policy: plain loads AND plain stores (best DRAM%: 88.1)
// MLP_p1=2 per thread (below the L1tex cross-CTA contention knee),
// 65536 blocks, occ ~91%.

static constexpr int ROW_IN  = 1024;
static constexpr int ROW_OUT = 512;
static constexpr int THREADS = 256;   // 2 rows x 128 threads

__global__ __launch_bounds__(THREADS)
void projection_kernel(const float* __restrict__ x,
                       float* __restrict__ out)
{
    int sub  = threadIdx.x >> 7;           // row group 0/1
    int tid  = threadIdx.x & 127;          // 0..127 within group
    int lane = threadIdx.x & 31;
    int warp = (threadIdx.x >> 5) & 3;     // warp within group

    size_t row = (size_t)blockIdx.x * 2 + sub;

    const float4* xrow = reinterpret_cast<const float4*>(x + row * ROW_IN);
    float4*       orow = reinterpret_cast<float4*>(out + row * ROW_OUT);

    // front-batch both loads, default cache policy (measured best)
    float4 t = xrow[128 + tid];   // tail, feeds reduction
    float4 h = xrow[tid];         // head, held for the add

    float s = (t.x + t.y) + (t.z + t.w);

    #pragma unroll
    for (int off = 16; off > 0; off >>= 1)
        s += __shfl_xor_sync(0xFFFFFFFFu, s, off);

    __shared__ float partial[2][4];
    if (lane == 0) partial[sub][warp] = s;
    __syncthreads();

    float total = (partial[sub][0] + partial[sub][1])
                + (partial[sub][2] + partial[sub][3]);
    float mean = total * (1.0f / 512.0f);

    h.x += mean; h.y += mean; h.z += mean; h.w += mean;

    orow[tid] = h;
}

extern "C" void kernel_launch(void* const* d_in, const int* in_sizes, int n_in,
                              void* d_out, int out_size)
{
    const float* x = (const float*)d_in[0];
    float* out = (float*)d_out;

    int n_rows = in_sizes[0] / ROW_IN;   // 131072, even
    int blocks = n_rows / 2;             // 65536

    projection_kernel<<<blocks, THREADS>>>(x, out);
}